// round 7
// baseline (speedup 1.0000x reference)
#include <cuda_runtime.h>

// ---------------------------------------------------------------------------
// TorchFovea R7: 5 launches.
//   gen_filters | pyrdown(images->dn1) | pyrdown(dn1->dn2)
//   fused_mid: dn2 -> dn3,dn4,dn5,F4,F3,F2 (smem) -> writes F2
//   recon0_fused: computes F1 tile on-the-fly from (F2,dn2,dn1), then
//                 out = pyrup(F1) + (images - pyrup(dn1)) * w0
// ---------------------------------------------------------------------------

#define NPL 96

#define H0 360
#define W0 640
#define H1 180
#define W1 320
#define H2 90
#define W2 160
#define H3 45
#define W3 80
#define H4 23
#define W4 40
#define H5 12
#define W5 20

#define ROWV_TOT (1279 + 640 + 320 + 160 + 80)
#define COLV_TOT (719 + 360 + 180 + 90 + 45)
#define RO0 0
#define RO1 1279
#define RO2 1919
#define RO3 2239
#define RO4 2399
#define CO0 0
#define CO1 719
#define CO2 1079
#define CO3 1259
#define CO4 1349

__device__ float g_rowv[ROWV_TOT];
__device__ float g_colv[COLV_TOT];
__device__ float g_dn1[NPL * H1 * W1];
__device__ float g_dn2[NPL * H2 * W2];
__device__ float g_F2[NPL * H2 * W2];

__device__ __forceinline__ int refl(int i, int n) {
    i = (i < 0) ? -i : i;
    return (i >= n) ? (2 * n - 2 - i) : i;
}

// ---------------------------------------------------------------------------
__device__ __forceinline__ float pd1_at(const float* __restrict__ v, int N, int o) {
    int x = 2 * o;
    return 0.375f * v[x]
         + 0.25f  * (v[refl(x - 1, N)] + v[refl(x + 1, N)])
         + 0.0625f * (v[refl(x - 2, N)] + v[refl(x + 2, N)]);
}

__global__ void gen_filters_kernel(float* __restrict__ rowv, float* __restrict__ colv) {
    const int t = threadIdx.x;
    const int NT = blockDim.x;
    for (int i = t; i < 1279; i += NT) {
        float d = (float)(i - 640);
        rowv[RO0 + i] = expf(-d * d / 10082.0f);
    }
    for (int j = t; j < 719; j += NT) {
        float d = (float)(j - 360);
        colv[CO0 + j] = expf(-d * d / 10082.0f);
    }
    __syncthreads();
    const int rN[5] = {1279, 640, 320, 160, 80};
    const int rO[5] = {RO0, RO1, RO2, RO3, RO4};
    const int cN[5] = {719, 360, 180, 90, 45};
    const int cO[5] = {CO0, CO1, CO2, CO3, CO4};
#pragma unroll
    for (int k = 1; k < 5; k++) {
        const float* ri = rowv + rO[k - 1];
        float* ro = rowv + rO[k];
        for (int o = t; o < rN[k]; o += NT) ro[o] = pd1_at(ri, rN[k - 1], o);
        const float* ci = colv + cO[k - 1];
        float* co = colv + cO[k];
        for (int o = t; o < cN[k]; o += NT) co[o] = pd1_at(ci, cN[k - 1], o);
        __syncthreads();
    }
}

// ---------------------------------------------------------------------------
// pyrDown: block (16,16) -> 32x16 output tile, float2 stores, smem staged.
// ---------------------------------------------------------------------------
#define PTX 32
#define PTY 16
#define PIW (2 * PTX + 4)   // 68
#define PIH (2 * PTY + 4)   // 36

__global__ void __launch_bounds__(256) pyrdown_st(
        const float* __restrict__ src, float* __restrict__ dst,
        int H, int W, int oH, int oW) {
    int c = blockIdx.z;
    const float* s = src + (size_t)c * H * W;
    float* d = dst + (size_t)c * oH * oW;
    int ox0 = blockIdx.x * PTX;
    int oy0 = blockIdx.y * PTY;

    __shared__ float in[PIH][PIW];
    __shared__ float hb[PIH][PTX];

    int tid = threadIdx.y * 16 + threadIdx.x;
    for (int idx = tid; idx < PIH * PIW; idx += 256) {
        int r = idx / PIW;
        int col = idx - r * PIW;
        int gy = refl(2 * oy0 - 2 + r, H);
        int gx = refl(2 * ox0 - 2 + col, W);
        in[r][col] = s[(size_t)gy * W + gx];
    }
    __syncthreads();

    const float k0 = 0.0625f, k1 = 0.25f, k2 = 0.375f;
    for (int idx = tid; idx < PIH * PTX; idx += 256) {
        int r = idx >> 5;
        int j = idx & 31;
        const float* row = in[r] + 2 * j;
        hb[r][j] = k0 * (row[0] + row[4]) + k1 * (row[1] + row[3]) + k2 * row[2];
    }
    __syncthreads();

    int oy = oy0 + threadIdx.y;
    int ox = ox0 + 2 * threadIdx.x;
    if (oy < oH && ox < oW) {
        int r = 2 * threadIdx.y;
        int j = 2 * threadIdx.x;
        float2 o;
        o.x = k0 * (hb[r][j] + hb[r + 4][j]) + k1 * (hb[r + 1][j] + hb[r + 3][j])
            + k2 * hb[r + 2][j];
        o.y = k0 * (hb[r][j + 1] + hb[r + 4][j + 1]) + k1 * (hb[r + 1][j + 1] + hb[r + 3][j + 1])
            + k2 * hb[r + 2][j + 1];
        *(float2*)(d + (size_t)oy * oW + ox) = o;
    }
}

// ---------------------------------------------------------------------------
__device__ __forceinline__ float pd2_at(const float* __restrict__ s, int H, int W,
                                        int y, int x) {
    int ry[5], rx[5];
#pragma unroll
    for (int i = 0; i < 5; i++) {
        ry[i] = refl(2 * y - 2 + i, H);
        rx[i] = refl(2 * x - 2 + i, W);
    }
    const float k0 = 0.0625f, k1 = 0.25f, k2 = 0.375f;
    float acc = 0.0f;
#pragma unroll
    for (int i = 0; i < 5; i++) {
        const float* row = s + ry[i] * W;
        float r = k2 * row[rx[2]]
                + k1 * (row[rx[1]] + row[rx[3]])
                + k0 * (row[rx[0]] + row[rx[4]]);
        float kw = (i == 2) ? k2 : ((i == 1 || i == 3) ? k1 : k0);
        acc += kw * r;
    }
    return acc;
}

__device__ __forceinline__ void pyrup_quad(const float* __restrict__ s, int H, int W,
                                           int qy, int qx,
                                           float& ee, float& eo, float& oe, float& oo) {
    int xl = (qx == 0) ? 1 : qx - 1;
    int xr = (qx < W - 1) ? qx + 1 : W - 1;
    int yu = (qy == 0) ? 1 : qy - 1;
    int yd = (qy < H - 1) ? qy + 1 : H - 1;
    const float* r0 = s + yu * W;
    const float* r1 = s + qy * W;
    const float* r2 = s + yd * W;
    float a00 = r0[xl], a01 = r0[qx], a02 = r0[xr];
    float a10 = r1[xl], a11 = r1[qx], a12 = r1[xr];
    float a20 = r2[xl], a21 = r2[qx], a22 = r2[xr];
    float he0 = 0.125f * (a00 + a02) + 0.75f * a01;
    float he1 = 0.125f * (a10 + a12) + 0.75f * a11;
    float he2 = 0.125f * (a20 + a22) + 0.75f * a21;
    float ho0 = 0.5f * (a01 + a02);
    float ho1 = 0.5f * (a11 + a12);
    float ho2 = 0.5f * (a21 + a22);
    ee = 0.125f * (he0 + he2) + 0.75f * he1;
    eo = 0.125f * (ho0 + ho2) + 0.75f * ho1;
    oe = 0.5f * (he1 + he2);
    oo = 0.5f * (ho1 + ho2);
}

// pointwise pyrup from a staged tile holding clamped-global values.
// tile origin (oy, ox) in source coords; row stride tW.
__device__ __forceinline__ float pyrup_loc(const float* __restrict__ s, int tW,
                                           int oy, int ox, int H, int W,
                                           int y, int x) {
    int sy0, sy1, sy2; float wy0, wy1, wy2;
    if ((y & 1) == 0) {
        sy0 = refl(y - 2, 2 * H) >> 1; wy0 = 0.125f;
        sy1 = y >> 1;                  wy1 = 0.75f;
        sy2 = refl(y + 2, 2 * H) >> 1; wy2 = 0.125f;
    } else {
        sy0 = (y - 1) >> 1;            wy0 = 0.5f;
        sy1 = refl(y + 1, 2 * H) >> 1; wy1 = 0.5f;
        sy2 = sy1;                     wy2 = 0.0f;
    }
    int sx0, sx1, sx2; float wx0, wx1, wx2;
    if ((x & 1) == 0) {
        sx0 = refl(x - 2, 2 * W) >> 1; wx0 = 0.125f;
        sx1 = x >> 1;                  wx1 = 0.75f;
        sx2 = refl(x + 2, 2 * W) >> 1; wx2 = 0.125f;
    } else {
        sx0 = (x - 1) >> 1;            wx0 = 0.5f;
        sx1 = refl(x + 1, 2 * W) >> 1; wx1 = 0.5f;
        sx2 = sx1;                     wx2 = 0.0f;
    }
    const float* r0 = s + (sy0 - oy) * tW - ox;
    const float* r1 = s + (sy1 - oy) * tW - ox;
    const float* r2 = s + (sy2 - oy) * tW - ox;
    float h0 = wx0 * r0[sx0] + wx1 * r0[sx1] + wx2 * r0[sx2];
    float h1 = wx0 * r1[sx0] + wx1 * r1[sx1] + wx2 * r1[sx2];
    float h2 = wx0 * r2[sx0] + wx1 * r2[sx1] + wx2 * r2[sx2];
    return wy0 * h0 + wy1 * h1 + wy2 * h2;
}

// ---------------------------------------------------------------------------
// Fused mid levels (1024-thread block per plane): dn2 -> dn3..dn5, F4, F3, F2.
// ---------------------------------------------------------------------------
#define FNT 1024
#define SM_DN2 0
#define SM_HB3 14400
#define SM_DN3 21600
#define SM_DN4 25200
#define SM_DN5 26120
#define SM_F4  26360
#define SM_TOT 27280   // 109120 bytes

__global__ void __launch_bounds__(FNT) fused_mid_kernel(
        const float* __restrict__ dn2,
        const float* __restrict__ colv, const float* __restrict__ rowv,
        const float* __restrict__ fixations,
        float* __restrict__ F2g) {
    extern __shared__ float sm[];
    float* s_dn2 = sm + SM_DN2;
    float* s_hb3 = sm + SM_HB3;
    float* s_F3  = sm + SM_HB3;
    float* s_dn3 = sm + SM_DN3;
    float* s_dn4 = sm + SM_DN4;
    float* s_dn5 = sm + SM_DN5;
    float* s_F4  = sm + SM_F4;

    const int p = blockIdx.x;
    const int b = p / 3;
    const int t = threadIdx.x;
    const float k0 = 0.0625f, k1 = 0.25f, k2 = 0.375f;

    const float4* src4 = (const float4*)(dn2 + (size_t)p * (H2 * W2));
    for (int i = t; i < (H2 * W2) / 4; i += FNT) ((float4*)s_dn2)[i] = src4[i];
    __syncthreads();

    for (int idx = t; idx < H2 * W3; idx += FNT) {
        int y = idx / W3;
        int ox = idx - y * W3;
        const float* row = s_dn2 + y * W2;
        int xc = 2 * ox;
        float v;
        if (ox >= 1 && ox <= W3 - 2) {
            v = k0 * (row[xc - 2] + row[xc + 2]) + k1 * (row[xc - 1] + row[xc + 1])
              + k2 * row[xc];
        } else {
            v = k2 * row[xc]
              + k1 * (row[refl(xc - 1, W2)] + row[refl(xc + 1, W2)])
              + k0 * (row[refl(xc - 2, W2)] + row[refl(xc + 2, W2)]);
        }
        s_hb3[idx] = v;
    }
    __syncthreads();

    for (int idx = t; idx < H3 * W3; idx += FNT) {
        int oy = idx / W3;
        int ox = idx - oy * W3;
        int yc = 2 * oy;
        float v;
        if (oy >= 1 && oy <= H3 - 2) {
            v = k0 * (s_hb3[(yc - 2) * W3 + ox] + s_hb3[(yc + 2) * W3 + ox])
              + k1 * (s_hb3[(yc - 1) * W3 + ox] + s_hb3[(yc + 1) * W3 + ox])
              + k2 * s_hb3[yc * W3 + ox];
        } else {
            v = k2 * s_hb3[yc * W3 + ox]
              + k1 * (s_hb3[refl(yc - 1, H2) * W3 + ox] + s_hb3[refl(yc + 1, H2) * W3 + ox])
              + k0 * (s_hb3[refl(yc - 2, H2) * W3 + ox] + s_hb3[refl(yc + 2, H2) * W3 + ox]);
        }
        s_dn3[idx] = v;
    }
    __syncthreads();

    for (int idx = t; idx < H4 * W4; idx += FNT)
        s_dn4[idx] = pd2_at(s_dn3, H3, W3, idx / W4, idx % W4);
    __syncthreads();
    for (int idx = t; idx < H5 * W5; idx += FNT)
        s_dn5[idx] = pd2_at(s_dn4, H4, W4, idx / W5, idx % W5);
    __syncthreads();

    const float fxx = fixations[2 * b];
    const float fyy = fixations[2 * b + 1];

    {   // level 4
        int x1 = min(max((int)(40.0f - fxx * 0.0625f), 0), W3 - W4);
        int y1 = min(max((int)(22.5f - fyy * 0.0625f), 0), H3 - H4);
        const float* cv = colv + CO4 + y1;
        const float* rv = rowv + RO4 + x1;
        const int qH = (H4 + 1) / 2, qW = W4 / 2;
        for (int idx = t; idx < qH * qW; idx += FNT) {
            int qy = idx / qW;
            int qx = idx - qy * qW;
            float ee, eo, oe, oo;
            pyrup_quad(s_dn5, H5, W5, qy, qx, ee, eo, oe, oo);
            int y0 = 2 * qy, x0 = 2 * qx;
            float rw0 = rv[x0], rw1 = rv[x0 + 1];
            float cw0 = cv[y0];
            s_F4[y0 * W4 + x0]     = ee + (s_dn4[y0 * W4 + x0]     - ee) * (cw0 * rw0);
            s_F4[y0 * W4 + x0 + 1] = eo + (s_dn4[y0 * W4 + x0 + 1] - eo) * (cw0 * rw1);
            if (y0 + 1 < H4) {
                float cw1 = cv[y0 + 1];
                s_F4[(y0 + 1) * W4 + x0]     = oe + (s_dn4[(y0 + 1) * W4 + x0]     - oe) * (cw1 * rw0);
                s_F4[(y0 + 1) * W4 + x0 + 1] = oo + (s_dn4[(y0 + 1) * W4 + x0 + 1] - oo) * (cw1 * rw1);
            }
        }
    }
    __syncthreads();

    {   // level 3
        int x1 = min(max((int)(80.0f - fxx * 0.125f), 0), W2 - W3);
        int y1 = min(max((int)(45.0f - fyy * 0.125f), 0), H2 - H3);
        const float* cv = colv + CO3 + y1;
        const float* rv = rowv + RO3 + x1;
        const int qH = (H3 + 1) / 2, qW = W3 / 2;
        for (int idx = t; idx < qH * qW; idx += FNT) {
            int qy = idx / qW;
            int qx = idx - qy * qW;
            float Fee, Feo, Foe, Foo, Dee, Deo, Doe, Doo;
            pyrup_quad(s_F4, H4, W4, qy, qx, Fee, Feo, Foe, Foo);
            pyrup_quad(s_dn4, H4, W4, qy, qx, Dee, Deo, Doe, Doo);
            int y0 = 2 * qy, x0 = 2 * qx;
            float rw0 = rv[x0], rw1 = rv[x0 + 1];
            float cw0 = cv[y0];
            s_F3[y0 * W3 + x0]     = Fee + (s_dn3[y0 * W3 + x0]     - Dee) * (cw0 * rw0);
            s_F3[y0 * W3 + x0 + 1] = Feo + (s_dn3[y0 * W3 + x0 + 1] - Deo) * (cw0 * rw1);
            if (y0 + 1 < H3) {
                float cw1 = cv[y0 + 1];
                s_F3[(y0 + 1) * W3 + x0]     = Foe + (s_dn3[(y0 + 1) * W3 + x0]     - Doe) * (cw1 * rw0);
                s_F3[(y0 + 1) * W3 + x0 + 1] = Foo + (s_dn3[(y0 + 1) * W3 + x0 + 1] - Doo) * (cw1 * rw1);
            }
        }
    }
    __syncthreads();

    {   // level 2 -> global F2
        int x1 = min(max((int)(160.0f - fxx * 0.25f), 0), W1 - W2);
        int y1 = min(max((int)(90.0f - fyy * 0.25f), 0), H1 - H2);
        const float* cv = colv + CO2 + y1;
        const float* rv = rowv + RO2 + x1;
        float* g = F2g + (size_t)p * (H2 * W2);
        const int qH = H2 / 2, qW = W2 / 2;
        for (int idx = t; idx < qH * qW; idx += FNT) {
            int qy = idx / qW;
            int qx = idx - qy * qW;
            float Fee, Feo, Foe, Foo, Dee, Deo, Doe, Doo;
            pyrup_quad(s_F3, H3, W3, qy, qx, Fee, Feo, Foe, Foo);
            pyrup_quad(s_dn3, H3, W3, qy, qx, Dee, Deo, Doe, Doo);
            int y0 = 2 * qy, x0 = 2 * qx;
            float rw0 = rv[x0], rw1 = rv[x0 + 1];
            float cw0 = cv[y0], cw1 = cv[y0 + 1];
            float2 o0, o1;
            o0.x = Fee + (s_dn2[y0 * W2 + x0]     - Dee) * (cw0 * rw0);
            o0.y = Feo + (s_dn2[y0 * W2 + x0 + 1] - Deo) * (cw0 * rw1);
            o1.x = Foe + (s_dn2[(y0 + 1) * W2 + x0]     - Doe) * (cw1 * rw0);
            o1.y = Foo + (s_dn2[(y0 + 1) * W2 + x0 + 1] - Doo) * (cw1 * rw1);
            *(float2*)(g + y0 * W2 + x0) = o0;
            *(float2*)(g + (y0 + 1) * W2 + x0) = o1;
        }
    }
}

// ---------------------------------------------------------------------------
// recon0_fused: block (16,16) -> 64x32 output pixels (32x16 quads).
// Computes F1 tile in smem from F2/dn2/dn1 tiles (level-1 recon fused in),
// then final level-0 recon with images as Dcur.
// ---------------------------------------------------------------------------
#define RQX 32
#define RQY 16
#define T1W 36   // staged dn1/F1 tile: 18 x 36 (34 cols used)
#define T2W 20   // staged F2/dn2 tile: 11 x 20 (19 cols used)

__global__ void __launch_bounds__(256) recon0_fused(
        const float* __restrict__ F2,
        const float* __restrict__ dn2,
        const float* __restrict__ dn1,
        const float* __restrict__ images,
        const float* __restrict__ colv,   // base (level 0 at CO0, level 1 at CO1)
        const float* __restrict__ rowv,
        const float* __restrict__ fixations,
        float* __restrict__ out) {
    __shared__ float sD1[18][T1W];
    __shared__ float sF1[18][T1W];
    __shared__ float sF2[11][T2W];
    __shared__ float sD2[11][T2W];

    const int p = blockIdx.z;
    const int b = p / 3;
    const int qx0 = blockIdx.x * RQX;   // level-1 pixel coords == level-0 quad coords
    const int qy0 = blockIdx.y * RQY;
    const int tid = threadIdx.y * 16 + threadIdx.x;

    const float fxx = fixations[2 * b];
    const float fyy = fixations[2 * b + 1];
    const int x1_0 = min(max((int)(639.5f - fxx), 0), 1279 - W0);
    const int y1_0 = min(max((int)(359.5f - fyy), 0), 719 - H0);
    const int x1_1 = min(max((int)(320.0f - fxx * 0.5f), 0), W0 - W1);
    const int y1_1 = min(max((int)(180.0f - fyy * 0.5f), 0), H0 - H1);

    // ---- stage dn1 (18x34) and F2/dn2 (11x19) -------------------------------
    {
        const float* s1 = dn1 + (size_t)p * (H1 * W1);
        for (int i = tid; i < 18 * 34; i += 256) {
            int r = i / 34;
            int c = i - r * 34;
            int gr = qy0 - 1 + r;
            gr = (gr < 0) ? -gr : gr;
            gr = min(gr, H1 - 1);
            int gc = qx0 - 1 + c;
            gc = (gc < 0) ? -gc : gc;
            gc = min(gc, W1 - 1);
            sD1[r][c] = s1[(size_t)gr * W1 + gc];
        }
        const int oy2 = (qy0 >> 1) - 1;
        const int ox2 = (qx0 >> 1) - 1;
        const float* sf = F2 + (size_t)p * (H2 * W2);
        const float* sd = dn2 + (size_t)p * (H2 * W2);
        for (int i = tid; i < 11 * 19; i += 256) {
            int r = i / 19;
            int c = i - r * 19;
            int gr = min(max(oy2 + r, 0), H2 - 1);
            int gc = min(max(ox2 + c, 0), W2 - 1);
            size_t off = (size_t)gr * W2 + gc;
            sF2[r][c] = sf[off];
            sD2[r][c] = sd[off];
        }
    }
    __syncthreads();

    // ---- compute F1 tile (level-1 recon, pointwise) -------------------------
    {
        const int oy2 = (qy0 >> 1) - 1;
        const int ox2 = (qx0 >> 1) - 1;
        const float* cv1 = colv + CO1 + y1_1;
        const float* rv1 = rowv + RO1 + x1_1;
        for (int i = tid; i < 18 * 34; i += 256) {
            int r = i / 34;
            int c = i - r * 34;
            int gy = qy0 - 1 + r;
            gy = (gy < 0) ? -gy : gy;
            gy = min(gy, H1 - 1);
            int gx = qx0 - 1 + c;
            gx = (gx < 0) ? -gx : gx;
            gx = min(gx, W1 - 1);
            float uF = pyrup_loc(&sF2[0][0], T2W, oy2, ox2, H2, W2, gy, gx);
            float uD = pyrup_loc(&sD2[0][0], T2W, oy2, ox2, H2, W2, gy, gx);
            float w = cv1[gy] * rv1[gx];
            sF1[r][c] = uF + (sD1[r][c] - uD) * w;
        }
    }
    __syncthreads();

    // ---- level-0 recon (two quads per thread, float4 rows) ------------------
    const int ty = threadIdx.y;
    const int qy = qy0 + ty;
    if (qy >= H1) return;
    const int qxA = qx0 + 2 * threadIdx.x;

    const int cb = 2 * threadIdx.x + 1;
    const int la = (qxA == 0) ? 2 : cb - 1;
    const int rb = (qxA + 1 < W1 - 1) ? cb + 2 : ((W1 - 1) - (qx0 - 1));
    const int rc = ty + 1;
    const int ru = (qy == 0) ? 2 : ty;
    const int rd = (qy < H1 - 1) ? ty + 2 : ty + 1;

    float FheA[3], FhoA[3], FheB[3], FhoB[3];
    float DheA[3], DhoA[3], DheB[3], DhoB[3];
    int rows[3] = {ru, rc, rd};
#pragma unroll
    for (int i = 0; i < 3; i++) {
        int r = rows[i];
        {
            float vl = sF1[r][la], v0 = sF1[r][cb], v1 = sF1[r][cb + 1], vr = sF1[r][rb];
            FheA[i] = 0.125f * (vl + v1) + 0.75f * v0;
            FhoA[i] = 0.5f * (v0 + v1);
            FheB[i] = 0.125f * (v0 + vr) + 0.75f * v1;
            FhoB[i] = 0.5f * (v1 + vr);
        }
        {
            float vl = sD1[r][la], v0 = sD1[r][cb], v1 = sD1[r][cb + 1], vr = sD1[r][rb];
            DheA[i] = 0.125f * (vl + v1) + 0.75f * v0;
            DhoA[i] = 0.5f * (v0 + v1);
            DheB[i] = 0.125f * (v0 + vr) + 0.75f * v1;
            DhoB[i] = 0.5f * (v1 + vr);
        }
    }

    const int x0 = 2 * qxA;
    const int y0 = 2 * qy;
    const size_t obase = (size_t)p * (H0 * W0);
    const float* rv = rowv + RO0 + x1_0 + x0;
    float rw0 = rv[0], rw1 = rv[1], rw2 = rv[2], rw3 = rv[3];
    float cw0 = colv[CO0 + y0 + y1_0], cw1 = colv[CO0 + y0 + 1 + y1_0];

    {
        float uF0 = 0.125f * (FheA[0] + FheA[2]) + 0.75f * FheA[1];
        float uF1 = 0.125f * (FhoA[0] + FhoA[2]) + 0.75f * FhoA[1];
        float uF2 = 0.125f * (FheB[0] + FheB[2]) + 0.75f * FheB[1];
        float uF3 = 0.125f * (FhoB[0] + FhoB[2]) + 0.75f * FhoB[1];
        float uD0 = 0.125f * (DheA[0] + DheA[2]) + 0.75f * DheA[1];
        float uD1 = 0.125f * (DhoA[0] + DhoA[2]) + 0.75f * DhoA[1];
        float uD2 = 0.125f * (DheB[0] + DheB[2]) + 0.75f * DheB[1];
        float uD3 = 0.125f * (DhoB[0] + DhoB[2]) + 0.75f * DhoB[1];
        const float4 dc = *(const float4*)(images + obase + (size_t)y0 * W0 + x0);
        float4 o;
        o.x = uF0 + (dc.x - uD0) * (cw0 * rw0);
        o.y = uF1 + (dc.y - uD1) * (cw0 * rw1);
        o.z = uF2 + (dc.z - uD2) * (cw0 * rw2);
        o.w = uF3 + (dc.w - uD3) * (cw0 * rw3);
        *(float4*)(out + obase + (size_t)y0 * W0 + x0) = o;
    }
    {
        float uF0 = 0.5f * (FheA[1] + FheA[2]);
        float uF1 = 0.5f * (FhoA[1] + FhoA[2]);
        float uF2 = 0.5f * (FheB[1] + FheB[2]);
        float uF3 = 0.5f * (FhoB[1] + FhoB[2]);
        float uD0 = 0.5f * (DheA[1] + DheA[2]);
        float uD1 = 0.5f * (DhoA[1] + DhoA[2]);
        float uD2 = 0.5f * (DheB[1] + DheB[2]);
        float uD3 = 0.5f * (DhoB[1] + DhoB[2]);
        const float4 dc = *(const float4*)(images + obase + (size_t)(y0 + 1) * W0 + x0);
        float4 o;
        o.x = uF0 + (dc.x - uD0) * (cw1 * rw0);
        o.y = uF1 + (dc.y - uD1) * (cw1 * rw1);
        o.z = uF2 + (dc.z - uD2) * (cw1 * rw2);
        o.w = uF3 + (dc.w - uD3) * (cw1 * rw3);
        *(float4*)(out + obase + (size_t)(y0 + 1) * W0 + x0) = o;
    }
}

// ---------------------------------------------------------------------------

static inline int idiv(int a, int b) { return (a + b - 1) / b; }

extern "C" void kernel_launch(void* const* d_in, const int* in_sizes, int n_in,
                              void* d_out, int out_size) {
    (void)in_sizes; (void)n_in; (void)out_size;
    const float* images = (const float*)d_in[0];
    const float* fix    = (const float*)d_in[1];
    float* out = (float*)d_out;

    float *rowv, *colv, *dn1, *dn2, *F2;
    cudaGetSymbolAddress((void**)&rowv, g_rowv);
    cudaGetSymbolAddress((void**)&colv, g_colv);
    cudaGetSymbolAddress((void**)&dn1, g_dn1);
    cudaGetSymbolAddress((void**)&dn2, g_dn2);
    cudaGetSymbolAddress((void**)&F2, g_F2);

    cudaFuncSetAttribute(fused_mid_kernel,
                         cudaFuncAttributeMaxDynamicSharedMemorySize,
                         SM_TOT * (int)sizeof(float));

    gen_filters_kernel<<<1, 1024>>>(rowv, colv);

    {
        dim3 blk(16, 16);
        dim3 g1(W1 / PTX, idiv(H1, PTY), NPL);
        pyrdown_st<<<g1, blk>>>(images, dn1, H0, W0, H1, W1);
        dim3 g2(W2 / PTX, idiv(H2, PTY), NPL);
        pyrdown_st<<<g2, blk>>>(dn1, dn2, H1, W1, H2, W2);
    }

    fused_mid_kernel<<<NPL, FNT, SM_TOT * (int)sizeof(float)>>>(
        dn2, colv, rowv, fix, F2);

    {
        dim3 blk(16, 16);
        dim3 g0((W0 / 2) / RQX, idiv(H0 / 2, RQY), NPL);   // (10, 12, 96)
        recon0_fused<<<g0, blk>>>(F2, dn2, dn1, images, colv, rowv, fix, out);
    }
}

// round 8
// speedup vs baseline: 1.1187x; 1.1187x over previous
#include <cuda_runtime.h>

// ---------------------------------------------------------------------------
// TorchFovea R8: R6 pipeline (6 launches) + widened float4 pyrdown tiles.
//   gen_filters | pyrdown(images->dn1) | pyrdown(dn1->dn2)
//   fused_mid: dn2 -> dn3,dn4,dn5,F4,F3,F2  (all in smem, writes only F2)
//   recon_pair level1 (F2,dn2,dn1 -> F1) | recon_pair level0 (-> out)
// ---------------------------------------------------------------------------

#define NPL 96

#define H0 360
#define W0 640
#define H1 180
#define W1 320
#define H2 90
#define W2 160
#define H3 45
#define W3 80
#define H4 23
#define W4 40
#define H5 12
#define W5 20

#define ROWV_TOT (1279 + 640 + 320 + 160 + 80)
#define COLV_TOT (719 + 360 + 180 + 90 + 45)
#define RO0 0
#define RO1 1279
#define RO2 1919
#define RO3 2239
#define RO4 2399
#define CO0 0
#define CO1 719
#define CO2 1079
#define CO3 1259
#define CO4 1349

__device__ float g_rowv[ROWV_TOT];
__device__ float g_colv[COLV_TOT];
__device__ float g_dn1[NPL * H1 * W1];
__device__ float g_dn2[NPL * H2 * W2];
__device__ float g_F2[NPL * H2 * W2];
__device__ float g_F1[NPL * H1 * W1];

__device__ __forceinline__ int refl(int i, int n) {
    i = (i < 0) ? -i : i;
    return (i >= n) ? (2 * n - 2 - i) : i;
}

// ---------------------------------------------------------------------------
__device__ __forceinline__ float pd1_at(const float* __restrict__ v, int N, int o) {
    int x = 2 * o;
    return 0.375f * v[x]
         + 0.25f  * (v[refl(x - 1, N)] + v[refl(x + 1, N)])
         + 0.0625f * (v[refl(x - 2, N)] + v[refl(x + 2, N)]);
}

__global__ void gen_filters_kernel(float* __restrict__ rowv, float* __restrict__ colv) {
    const int t = threadIdx.x;
    const int NT = blockDim.x;
    for (int i = t; i < 1279; i += NT) {
        float d = (float)(i - 640);
        rowv[RO0 + i] = expf(-d * d / 10082.0f);
    }
    for (int j = t; j < 719; j += NT) {
        float d = (float)(j - 360);
        colv[CO0 + j] = expf(-d * d / 10082.0f);
    }
    __syncthreads();
    const int rN[5] = {1279, 640, 320, 160, 80};
    const int rO[5] = {RO0, RO1, RO2, RO3, RO4};
    const int cN[5] = {719, 360, 180, 90, 45};
    const int cO[5] = {CO0, CO1, CO2, CO3, CO4};
#pragma unroll
    for (int k = 1; k < 5; k++) {
        const float* ri = rowv + rO[k - 1];
        float* ro = rowv + rO[k];
        for (int o = t; o < rN[k]; o += NT) ro[o] = pd1_at(ri, rN[k - 1], o);
        const float* ci = colv + cO[k - 1];
        float* co = colv + cO[k];
        for (int o = t; o < cN[k]; o += NT) co[o] = pd1_at(ci, cN[k - 1], o);
        __syncthreads();
    }
}

// ---------------------------------------------------------------------------
// pyrDown v3: block (16,16) -> 64x16 output tile, float4 stores.
// Full input tile (36 x 132) staged coalesced, separable conv in smem.
// ---------------------------------------------------------------------------
#define PTX 64   // out tile width
#define PTY 16   // out tile height
#define PIW (2 * PTX + 4)   // 132
#define PIH (2 * PTY + 4)   // 36

__global__ void __launch_bounds__(256) pyrdown_st(
        const float* __restrict__ src, float* __restrict__ dst,
        int H, int W, int oH, int oW) {
    int c = blockIdx.z;
    const float* s = src + (size_t)c * H * W;
    float* d = dst + (size_t)c * oH * oW;
    int ox0 = blockIdx.x * PTX;
    int oy0 = blockIdx.y * PTY;

    __shared__ float in[PIH][PIW];
    __shared__ float hb[PIH][PTX];

    int tid = threadIdx.y * 16 + threadIdx.x;
    for (int idx = tid; idx < PIH * PIW; idx += 256) {
        int r = idx / PIW;
        int col = idx - r * PIW;
        int gy = refl(2 * oy0 - 2 + r, H);
        int gx = refl(2 * ox0 - 2 + col, W);
        in[r][col] = s[(size_t)gy * W + gx];
    }
    __syncthreads();

    const float k0 = 0.0625f, k1 = 0.25f, k2 = 0.375f;
    for (int idx = tid; idx < PIH * PTX; idx += 256) {
        int r = idx >> 6;
        int j = idx & 63;
        const float* row = in[r] + 2 * j;
        hb[r][j] = k0 * (row[0] + row[4]) + k1 * (row[1] + row[3]) + k2 * row[2];
    }
    __syncthreads();

    int oy = oy0 + threadIdx.y;
    int ox = ox0 + 4 * threadIdx.x;
    if (oy < oH && ox < oW) {
        int r = 2 * threadIdx.y;
        int j = 4 * threadIdx.x;
        float4 o;
        o.x = k0 * (hb[r][j] + hb[r + 4][j]) + k1 * (hb[r + 1][j] + hb[r + 3][j]) + k2 * hb[r + 2][j];
        o.y = k0 * (hb[r][j + 1] + hb[r + 4][j + 1]) + k1 * (hb[r + 1][j + 1] + hb[r + 3][j + 1]) + k2 * hb[r + 2][j + 1];
        o.z = k0 * (hb[r][j + 2] + hb[r + 4][j + 2]) + k1 * (hb[r + 1][j + 2] + hb[r + 3][j + 2]) + k2 * hb[r + 2][j + 2];
        o.w = k0 * (hb[r][j + 3] + hb[r + 4][j + 3]) + k1 * (hb[r + 1][j + 3] + hb[r + 3][j + 3]) + k2 * hb[r + 2][j + 3];
        if (ox + 3 < oW) {
            *(float4*)(d + (size_t)oy * oW + ox) = o;
        } else {
            float vv[4] = {o.x, o.y, o.z, o.w};
            for (int k = 0; k < 4 && ox + k < oW; k++) d[(size_t)oy * oW + ox + k] = vv[k];
        }
    }
}

// ---------------------------------------------------------------------------
__device__ __forceinline__ float pd2_at(const float* __restrict__ s, int H, int W,
                                        int y, int x) {
    int ry[5], rx[5];
#pragma unroll
    for (int i = 0; i < 5; i++) {
        ry[i] = refl(2 * y - 2 + i, H);
        rx[i] = refl(2 * x - 2 + i, W);
    }
    const float k0 = 0.0625f, k1 = 0.25f, k2 = 0.375f;
    float acc = 0.0f;
#pragma unroll
    for (int i = 0; i < 5; i++) {
        const float* row = s + ry[i] * W;
        float r = k2 * row[rx[2]]
                + k1 * (row[rx[1]] + row[rx[3]])
                + k0 * (row[rx[0]] + row[rx[4]]);
        float kw = (i == 2) ? k2 : ((i == 1 || i == 3) ? k1 : k0);
        acc += kw * r;
    }
    return acc;
}

__device__ __forceinline__ void pyrup_quad(const float* __restrict__ s, int H, int W,
                                           int qy, int qx,
                                           float& ee, float& eo, float& oe, float& oo) {
    int xl = (qx == 0) ? 1 : qx - 1;
    int xr = (qx < W - 1) ? qx + 1 : W - 1;
    int yu = (qy == 0) ? 1 : qy - 1;
    int yd = (qy < H - 1) ? qy + 1 : H - 1;
    const float* r0 = s + yu * W;
    const float* r1 = s + qy * W;
    const float* r2 = s + yd * W;
    float a00 = r0[xl], a01 = r0[qx], a02 = r0[xr];
    float a10 = r1[xl], a11 = r1[qx], a12 = r1[xr];
    float a20 = r2[xl], a21 = r2[qx], a22 = r2[xr];
    float he0 = 0.125f * (a00 + a02) + 0.75f * a01;
    float he1 = 0.125f * (a10 + a12) + 0.75f * a11;
    float he2 = 0.125f * (a20 + a22) + 0.75f * a21;
    float ho0 = 0.5f * (a01 + a02);
    float ho1 = 0.5f * (a11 + a12);
    float ho2 = 0.5f * (a21 + a22);
    ee = 0.125f * (he0 + he2) + 0.75f * he1;
    eo = 0.125f * (ho0 + ho2) + 0.75f * ho1;
    oe = 0.5f * (he1 + he2);
    oo = 0.5f * (ho1 + ho2);
}

// ---------------------------------------------------------------------------
// Fused mid levels (1024-thread block per plane): dn2 -> dn3,dn4,dn5,F4,F3,F2.
// Only F2 goes to global. smem: dn2 | hb3(/F3 overlay) | dn3 | dn4 | dn5 | F4
// ---------------------------------------------------------------------------
#define FNT 1024
#define SM_DN2 0
#define SM_HB3 14400
#define SM_DN3 21600
#define SM_DN4 25200
#define SM_DN5 26120
#define SM_F4  26360
#define SM_TOT 27280   // 109120 bytes

__global__ void __launch_bounds__(FNT) fused_mid_kernel(
        const float* __restrict__ dn2,
        const float* __restrict__ colv, const float* __restrict__ rowv,
        const float* __restrict__ fixations,
        float* __restrict__ F2g) {
    extern __shared__ float sm[];
    float* s_dn2 = sm + SM_DN2;
    float* s_hb3 = sm + SM_HB3;
    float* s_F3  = sm + SM_HB3;   // overlay (hb3 dead after dn3)
    float* s_dn3 = sm + SM_DN3;
    float* s_dn4 = sm + SM_DN4;
    float* s_dn5 = sm + SM_DN5;
    float* s_F4  = sm + SM_F4;

    const int p = blockIdx.x;
    const int b = p / 3;
    const int t = threadIdx.x;
    const float k0 = 0.0625f, k1 = 0.25f, k2 = 0.375f;

    const float4* src4 = (const float4*)(dn2 + (size_t)p * (H2 * W2));
    for (int i = t; i < (H2 * W2) / 4; i += FNT) ((float4*)s_dn2)[i] = src4[i];
    __syncthreads();

    for (int idx = t; idx < H2 * W3; idx += FNT) {
        int y = idx / W3;
        int ox = idx - y * W3;
        const float* row = s_dn2 + y * W2;
        int xc = 2 * ox;
        float v;
        if (ox >= 1 && ox <= W3 - 2) {
            v = k0 * (row[xc - 2] + row[xc + 2]) + k1 * (row[xc - 1] + row[xc + 1])
              + k2 * row[xc];
        } else {
            v = k2 * row[xc]
              + k1 * (row[refl(xc - 1, W2)] + row[refl(xc + 1, W2)])
              + k0 * (row[refl(xc - 2, W2)] + row[refl(xc + 2, W2)]);
        }
        s_hb3[idx] = v;
    }
    __syncthreads();

    for (int idx = t; idx < H3 * W3; idx += FNT) {
        int oy = idx / W3;
        int ox = idx - oy * W3;
        int yc = 2 * oy;
        float v;
        if (oy >= 1 && oy <= H3 - 2) {
            v = k0 * (s_hb3[(yc - 2) * W3 + ox] + s_hb3[(yc + 2) * W3 + ox])
              + k1 * (s_hb3[(yc - 1) * W3 + ox] + s_hb3[(yc + 1) * W3 + ox])
              + k2 * s_hb3[yc * W3 + ox];
        } else {
            v = k2 * s_hb3[yc * W3 + ox]
              + k1 * (s_hb3[refl(yc - 1, H2) * W3 + ox] + s_hb3[refl(yc + 1, H2) * W3 + ox])
              + k0 * (s_hb3[refl(yc - 2, H2) * W3 + ox] + s_hb3[refl(yc + 2, H2) * W3 + ox]);
        }
        s_dn3[idx] = v;
    }
    __syncthreads();

    for (int idx = t; idx < H4 * W4; idx += FNT)
        s_dn4[idx] = pd2_at(s_dn3, H3, W3, idx / W4, idx % W4);
    __syncthreads();
    for (int idx = t; idx < H5 * W5; idx += FNT)
        s_dn5[idx] = pd2_at(s_dn4, H4, W4, idx / W5, idx % W5);
    __syncthreads();

    const float fxx = fixations[2 * b];
    const float fyy = fixations[2 * b + 1];

    {   // level 4
        int x1 = min(max((int)(40.0f - fxx * 0.0625f), 0), W3 - W4);
        int y1 = min(max((int)(22.5f - fyy * 0.0625f), 0), H3 - H4);
        const float* cv = colv + CO4 + y1;
        const float* rv = rowv + RO4 + x1;
        const int qH = (H4 + 1) / 2, qW = W4 / 2;
        for (int idx = t; idx < qH * qW; idx += FNT) {
            int qy = idx / qW;
            int qx = idx - qy * qW;
            float ee, eo, oe, oo;
            pyrup_quad(s_dn5, H5, W5, qy, qx, ee, eo, oe, oo);
            int y0 = 2 * qy, x0 = 2 * qx;
            float rw0 = rv[x0], rw1 = rv[x0 + 1];
            float cw0 = cv[y0];
            s_F4[y0 * W4 + x0]     = ee + (s_dn4[y0 * W4 + x0]     - ee) * (cw0 * rw0);
            s_F4[y0 * W4 + x0 + 1] = eo + (s_dn4[y0 * W4 + x0 + 1] - eo) * (cw0 * rw1);
            if (y0 + 1 < H4) {
                float cw1 = cv[y0 + 1];
                s_F4[(y0 + 1) * W4 + x0]     = oe + (s_dn4[(y0 + 1) * W4 + x0]     - oe) * (cw1 * rw0);
                s_F4[(y0 + 1) * W4 + x0 + 1] = oo + (s_dn4[(y0 + 1) * W4 + x0 + 1] - oo) * (cw1 * rw1);
            }
        }
    }
    __syncthreads();

    {   // level 3
        int x1 = min(max((int)(80.0f - fxx * 0.125f), 0), W2 - W3);
        int y1 = min(max((int)(45.0f - fyy * 0.125f), 0), H2 - H3);
        const float* cv = colv + CO3 + y1;
        const float* rv = rowv + RO3 + x1;
        const int qH = (H3 + 1) / 2, qW = W3 / 2;
        for (int idx = t; idx < qH * qW; idx += FNT) {
            int qy = idx / qW;
            int qx = idx - qy * qW;
            float Fee, Feo, Foe, Foo, Dee, Deo, Doe, Doo;
            pyrup_quad(s_F4, H4, W4, qy, qx, Fee, Feo, Foe, Foo);
            pyrup_quad(s_dn4, H4, W4, qy, qx, Dee, Deo, Doe, Doo);
            int y0 = 2 * qy, x0 = 2 * qx;
            float rw0 = rv[x0], rw1 = rv[x0 + 1];
            float cw0 = cv[y0];
            s_F3[y0 * W3 + x0]     = Fee + (s_dn3[y0 * W3 + x0]     - Dee) * (cw0 * rw0);
            s_F3[y0 * W3 + x0 + 1] = Feo + (s_dn3[y0 * W3 + x0 + 1] - Deo) * (cw0 * rw1);
            if (y0 + 1 < H3) {
                float cw1 = cv[y0 + 1];
                s_F3[(y0 + 1) * W3 + x0]     = Foe + (s_dn3[(y0 + 1) * W3 + x0]     - Doe) * (cw1 * rw0);
                s_F3[(y0 + 1) * W3 + x0 + 1] = Foo + (s_dn3[(y0 + 1) * W3 + x0 + 1] - Doo) * (cw1 * rw1);
            }
        }
    }
    __syncthreads();

    {   // level 2 -> global F2
        int x1 = min(max((int)(160.0f - fxx * 0.25f), 0), W1 - W2);
        int y1 = min(max((int)(90.0f - fyy * 0.25f), 0), H1 - H2);
        const float* cv = colv + CO2 + y1;
        const float* rv = rowv + RO2 + x1;
        float* g = F2g + (size_t)p * (H2 * W2);
        const int qH = H2 / 2, qW = W2 / 2;
        for (int idx = t; idx < qH * qW; idx += FNT) {
            int qy = idx / qW;
            int qx = idx - qy * qW;
            float Fee, Feo, Foe, Foo, Dee, Deo, Doe, Doo;
            pyrup_quad(s_F3, H3, W3, qy, qx, Fee, Feo, Foe, Foo);
            pyrup_quad(s_dn3, H3, W3, qy, qx, Dee, Deo, Doe, Doo);
            int y0 = 2 * qy, x0 = 2 * qx;
            float rw0 = rv[x0], rw1 = rv[x0 + 1];
            float cw0 = cv[y0], cw1 = cv[y0 + 1];
            float2 o0, o1;
            o0.x = Fee + (s_dn2[y0 * W2 + x0]     - Dee) * (cw0 * rw0);
            o0.y = Feo + (s_dn2[y0 * W2 + x0 + 1] - Deo) * (cw0 * rw1);
            o1.x = Foe + (s_dn2[(y0 + 1) * W2 + x0]     - Doe) * (cw1 * rw0);
            o1.y = Foo + (s_dn2[(y0 + 1) * W2 + x0 + 1] - Doo) * (cw1 * rw1);
            *(float2*)(g + y0 * W2 + x0) = o0;
            *(float2*)(g + (y0 + 1) * W2 + x0) = o1;
        }
    }
}

// ---------------------------------------------------------------------------
// recon_pair: each thread computes TWO adjacent quads = a 4x2 output block
// (float4 rows). Block (16,16) -> 64x32 output tile.
// ---------------------------------------------------------------------------
#define RQX 32   // quads per tile (x)
#define RQY 16   // quads per tile (y)

__global__ void __launch_bounds__(256) recon_pair(
        const float* __restrict__ Fsrc,
        const float* __restrict__ Dnext,
        int sH, int sW,
        const float* __restrict__ Dcur,
        const float* __restrict__ colv,
        const float* __restrict__ rowv,
        int fH, int fW,
        const float* __restrict__ fixations,
        float invscale,
        float* __restrict__ out, int oH, int oW) {
    __shared__ float sF[RQY + 2][RQX + 2];
    __shared__ float sD[RQY + 2][RQX + 2];

    const int p = blockIdx.z;
    const int b = p / 3;
    const int qx0 = blockIdx.x * RQX;
    const int qy0 = blockIdx.y * RQY;
    const size_t soff = (size_t)p * sH * sW;

    int tid = threadIdx.y * 16 + threadIdx.x;
    for (int i = tid; i < (RQY + 2) * (RQX + 2); i += 256) {
        int r = i / (RQX + 2);
        int c2 = i - r * (RQX + 2);
        int gr = qy0 - 1 + r;
        gr = (gr < 0) ? -gr : gr;
        gr = min(gr, sH - 1);
        int gc = qx0 - 1 + c2;
        gc = (gc < 0) ? -gc : gc;
        gc = min(gc, sW - 1);
        size_t off = soff + (size_t)gr * sW + gc;
        sF[r][c2] = Fsrc[off];
        sD[r][c2] = Dnext[off];
    }
    __syncthreads();

    const int ty = threadIdx.y;
    const int qy = qy0 + ty;
    if (qy >= sH) return;
    const int qxA = qx0 + 2 * threadIdx.x;

    float fx = fixations[2 * b]     * invscale;
    float fy = fixations[2 * b + 1] * invscale;
    int x1 = min(max((int)((float)fW * 0.5f - fx), 0), fW - oW);
    int y1 = min(max((int)((float)fH * 0.5f - fy), 0), fH - oH);

    const int cb = 2 * threadIdx.x + 1;
    const int la = (qxA == 0) ? 2 : cb - 1;
    const int rb = (qxA + 1 < sW - 1) ? cb + 2 : ((sW - 1) - (qx0 - 1));
    const int rc = ty + 1;
    const int ru = (qy == 0) ? 2 : ty;
    const int rd = (qy < sH - 1) ? ty + 2 : ty + 1;

    float FheA[3], FhoA[3], FheB[3], FhoB[3];
    float DheA[3], DhoA[3], DheB[3], DhoB[3];
    int rows[3] = {ru, rc, rd};
#pragma unroll
    for (int i = 0; i < 3; i++) {
        int r = rows[i];
        {
            float vl = sF[r][la], v0 = sF[r][cb], v1 = sF[r][cb + 1], vr = sF[r][rb];
            FheA[i] = 0.125f * (vl + v1) + 0.75f * v0;
            FhoA[i] = 0.5f * (v0 + v1);
            FheB[i] = 0.125f * (v0 + vr) + 0.75f * v1;
            FhoB[i] = 0.5f * (v1 + vr);
        }
        {
            float vl = sD[r][la], v0 = sD[r][cb], v1 = sD[r][cb + 1], vr = sD[r][rb];
            DheA[i] = 0.125f * (vl + v1) + 0.75f * v0;
            DhoA[i] = 0.5f * (v0 + v1);
            DheB[i] = 0.125f * (v0 + vr) + 0.75f * v1;
            DhoB[i] = 0.5f * (v1 + vr);
        }
    }

    const int x0 = 2 * qxA;
    const int y0 = 2 * qy;
    const size_t obase = (size_t)p * oH * oW;
    const float* rv = rowv + x1 + x0;
    float rw0 = rv[0], rw1 = rv[1], rw2 = rv[2], rw3 = rv[3];
    float cw0 = colv[y0 + y1], cw1 = colv[y0 + 1 + y1];

    {
        float uF0 = 0.125f * (FheA[0] + FheA[2]) + 0.75f * FheA[1];
        float uF1 = 0.125f * (FhoA[0] + FhoA[2]) + 0.75f * FhoA[1];
        float uF2 = 0.125f * (FheB[0] + FheB[2]) + 0.75f * FheB[1];
        float uF3 = 0.125f * (FhoB[0] + FhoB[2]) + 0.75f * FhoB[1];
        float uD0 = 0.125f * (DheA[0] + DheA[2]) + 0.75f * DheA[1];
        float uD1 = 0.125f * (DhoA[0] + DhoA[2]) + 0.75f * DhoA[1];
        float uD2 = 0.125f * (DheB[0] + DheB[2]) + 0.75f * DheB[1];
        float uD3 = 0.125f * (DhoB[0] + DhoB[2]) + 0.75f * DhoB[1];
        const float4 dc = *(const float4*)(Dcur + obase + (size_t)y0 * oW + x0);
        float4 o;
        o.x = uF0 + (dc.x - uD0) * (cw0 * rw0);
        o.y = uF1 + (dc.y - uD1) * (cw0 * rw1);
        o.z = uF2 + (dc.z - uD2) * (cw0 * rw2);
        o.w = uF3 + (dc.w - uD3) * (cw0 * rw3);
        *(float4*)(out + obase + (size_t)y0 * oW + x0) = o;
    }
    {
        float uF0 = 0.5f * (FheA[1] + FheA[2]);
        float uF1 = 0.5f * (FhoA[1] + FhoA[2]);
        float uF2 = 0.5f * (FheB[1] + FheB[2]);
        float uF3 = 0.5f * (FhoB[1] + FhoB[2]);
        float uD0 = 0.5f * (DheA[1] + DheA[2]);
        float uD1 = 0.5f * (DhoA[1] + DhoA[2]);
        float uD2 = 0.5f * (DheB[1] + DheB[2]);
        float uD3 = 0.5f * (DhoB[1] + DhoB[2]);
        const float4 dc = *(const float4*)(Dcur + obase + (size_t)(y0 + 1) * oW + x0);
        float4 o;
        o.x = uF0 + (dc.x - uD0) * (cw1 * rw0);
        o.y = uF1 + (dc.y - uD1) * (cw1 * rw1);
        o.z = uF2 + (dc.z - uD2) * (cw1 * rw2);
        o.w = uF3 + (dc.w - uD3) * (cw1 * rw3);
        *(float4*)(out + obase + (size_t)(y0 + 1) * oW + x0) = o;
    }
}

// ---------------------------------------------------------------------------

static inline int idiv(int a, int b) { return (a + b - 1) / b; }

extern "C" void kernel_launch(void* const* d_in, const int* in_sizes, int n_in,
                              void* d_out, int out_size) {
    (void)in_sizes; (void)n_in; (void)out_size;
    const float* images = (const float*)d_in[0];
    const float* fix    = (const float*)d_in[1];
    float* out = (float*)d_out;

    float *rowv, *colv, *dn1, *dn2, *F2, *F1;
    cudaGetSymbolAddress((void**)&rowv, g_rowv);
    cudaGetSymbolAddress((void**)&colv, g_colv);
    cudaGetSymbolAddress((void**)&dn1, g_dn1);
    cudaGetSymbolAddress((void**)&dn2, g_dn2);
    cudaGetSymbolAddress((void**)&F2, g_F2);
    cudaGetSymbolAddress((void**)&F1, g_F1);

    cudaFuncSetAttribute(fused_mid_kernel,
                         cudaFuncAttributeMaxDynamicSharedMemorySize,
                         SM_TOT * (int)sizeof(float));

    gen_filters_kernel<<<1, 1024>>>(rowv, colv);

    {
        dim3 blk(16, 16);
        dim3 g1(idiv(W1, PTX), idiv(H1, PTY), NPL);   // (5, 12, 96)
        pyrdown_st<<<g1, blk>>>(images, dn1, H0, W0, H1, W1);
        dim3 g2(idiv(W2, PTX), idiv(H2, PTY), NPL);   // (3, 6, 96)
        pyrdown_st<<<g2, blk>>>(dn1, dn2, H1, W1, H2, W2);
    }

    fused_mid_kernel<<<NPL, FNT, SM_TOT * (int)sizeof(float)>>>(
        dn2, colv, rowv, fix, F2);

    {
        dim3 blk(16, 16);
        dim3 g1((W1 / 2) / RQX, idiv(H1 / 2, RQY), NPL);   // (5, 6, 96)
        recon_pair<<<g1, blk>>>(F2, dn2, H2, W2, dn1,
                                colv + CO1, rowv + RO1, H0, W0,
                                fix, 0.5f, F1, H1, W1);
        dim3 g0((W0 / 2) / RQX, idiv(H0 / 2, RQY), NPL);   // (10, 12, 96)
        recon_pair<<<g0, blk>>>(F1, dn1, H1, W1, images,
                                colv + CO0, rowv + RO0, 719, 1279,
                                fix, 1.0f, out, H0, W0);
    }
}

// round 9
// speedup vs baseline: 1.1844x; 1.0587x over previous
#include <cuda_runtime.h>

// ---------------------------------------------------------------------------
// TorchFovea R9: 5 launches.
//   gen_filters | pyrdown(images->dn1) | pyrdown(dn1->dn2)
//   fused_mid: dn2 -> dn3,dn4,dn5,F4,F3,F2 (smem) -> writes F2
//   recon01: per block, compute F1 tile (quad-structured, smem) from
//            F2/dn2/dn1, then level-0 recon vs images -> out.
// ---------------------------------------------------------------------------

#define NPL 96

#define H0 360
#define W0 640
#define H1 180
#define W1 320
#define H2 90
#define W2 160
#define H3 45
#define W3 80
#define H4 23
#define W4 40
#define H5 12
#define W5 20

#define ROWV_TOT (1279 + 640 + 320 + 160 + 80)
#define COLV_TOT (719 + 360 + 180 + 90 + 45)
#define RO0 0
#define RO1 1279
#define RO2 1919
#define RO3 2239
#define RO4 2399
#define CO0 0
#define CO1 719
#define CO2 1079
#define CO3 1259
#define CO4 1349

__device__ float g_rowv[ROWV_TOT];
__device__ float g_colv[COLV_TOT];
__device__ float g_dn1[NPL * H1 * W1];
__device__ float g_dn2[NPL * H2 * W2];
__device__ float g_F2[NPL * H2 * W2];

__device__ __forceinline__ int refl(int i, int n) {
    i = (i < 0) ? -i : i;
    return (i >= n) ? (2 * n - 2 - i) : i;
}

// ---------------------------------------------------------------------------
__device__ __forceinline__ float pd1_at(const float* __restrict__ v, int N, int o) {
    int x = 2 * o;
    return 0.375f * v[x]
         + 0.25f  * (v[refl(x - 1, N)] + v[refl(x + 1, N)])
         + 0.0625f * (v[refl(x - 2, N)] + v[refl(x + 2, N)]);
}

__global__ void gen_filters_kernel(float* __restrict__ rowv, float* __restrict__ colv) {
    const int t = threadIdx.x;
    const int NT = blockDim.x;
    for (int i = t; i < 1279; i += NT) {
        float d = (float)(i - 640);
        rowv[RO0 + i] = expf(-d * d / 10082.0f);
    }
    for (int j = t; j < 719; j += NT) {
        float d = (float)(j - 360);
        colv[CO0 + j] = expf(-d * d / 10082.0f);
    }
    __syncthreads();
    const int rN[5] = {1279, 640, 320, 160, 80};
    const int rO[5] = {RO0, RO1, RO2, RO3, RO4};
    const int cN[5] = {719, 360, 180, 90, 45};
    const int cO[5] = {CO0, CO1, CO2, CO3, CO4};
#pragma unroll
    for (int k = 1; k < 5; k++) {
        const float* ri = rowv + rO[k - 1];
        float* ro = rowv + rO[k];
        for (int o = t; o < rN[k]; o += NT) ro[o] = pd1_at(ri, rN[k - 1], o);
        const float* ci = colv + cO[k - 1];
        float* co = colv + cO[k];
        for (int o = t; o < cN[k]; o += NT) co[o] = pd1_at(ci, cN[k - 1], o);
        __syncthreads();
    }
}

// ---------------------------------------------------------------------------
// pyrDown (R6 version): block (16,16) -> 32x16 output tile, float2 stores.
// ---------------------------------------------------------------------------
#define PTX 32
#define PTY 16
#define PIW (2 * PTX + 4)   // 68
#define PIH (2 * PTY + 4)   // 36

__global__ void __launch_bounds__(256) pyrdown_st(
        const float* __restrict__ src, float* __restrict__ dst,
        int H, int W, int oH, int oW) {
    int c = blockIdx.z;
    const float* s = src + (size_t)c * H * W;
    float* d = dst + (size_t)c * oH * oW;
    int ox0 = blockIdx.x * PTX;
    int oy0 = blockIdx.y * PTY;

    __shared__ float in[PIH][PIW];
    __shared__ float hb[PIH][PTX];

    int tid = threadIdx.y * 16 + threadIdx.x;
    for (int idx = tid; idx < PIH * PIW; idx += 256) {
        int r = idx / PIW;
        int col = idx - r * PIW;
        int gy = refl(2 * oy0 - 2 + r, H);
        int gx = refl(2 * ox0 - 2 + col, W);
        in[r][col] = s[(size_t)gy * W + gx];
    }
    __syncthreads();

    const float k0 = 0.0625f, k1 = 0.25f, k2 = 0.375f;
    for (int idx = tid; idx < PIH * PTX; idx += 256) {
        int r = idx >> 5;
        int j = idx & 31;
        const float* row = in[r] + 2 * j;
        hb[r][j] = k0 * (row[0] + row[4]) + k1 * (row[1] + row[3]) + k2 * row[2];
    }
    __syncthreads();

    int oy = oy0 + threadIdx.y;
    int ox = ox0 + 2 * threadIdx.x;
    if (oy < oH && ox < oW) {
        int r = 2 * threadIdx.y;
        int j = 2 * threadIdx.x;
        float2 o;
        o.x = k0 * (hb[r][j] + hb[r + 4][j]) + k1 * (hb[r + 1][j] + hb[r + 3][j])
            + k2 * hb[r + 2][j];
        o.y = k0 * (hb[r][j + 1] + hb[r + 4][j + 1]) + k1 * (hb[r + 1][j + 1] + hb[r + 3][j + 1])
            + k2 * hb[r + 2][j + 1];
        *(float2*)(d + (size_t)oy * oW + ox) = o;
    }
}

// ---------------------------------------------------------------------------
__device__ __forceinline__ float pd2_at(const float* __restrict__ s, int H, int W,
                                        int y, int x) {
    int ry[5], rx[5];
#pragma unroll
    for (int i = 0; i < 5; i++) {
        ry[i] = refl(2 * y - 2 + i, H);
        rx[i] = refl(2 * x - 2 + i, W);
    }
    const float k0 = 0.0625f, k1 = 0.25f, k2 = 0.375f;
    float acc = 0.0f;
#pragma unroll
    for (int i = 0; i < 5; i++) {
        const float* row = s + ry[i] * W;
        float r = k2 * row[rx[2]]
                + k1 * (row[rx[1]] + row[rx[3]])
                + k0 * (row[rx[0]] + row[rx[4]]);
        float kw = (i == 2) ? k2 : ((i == 1 || i == 3) ? k1 : k0);
        acc += kw * r;
    }
    return acc;
}

__device__ __forceinline__ void pyrup_quad(const float* __restrict__ s, int H, int W,
                                           int qy, int qx,
                                           float& ee, float& eo, float& oe, float& oo) {
    int xl = (qx == 0) ? 1 : qx - 1;
    int xr = (qx < W - 1) ? qx + 1 : W - 1;
    int yu = (qy == 0) ? 1 : qy - 1;
    int yd = (qy < H - 1) ? qy + 1 : H - 1;
    const float* r0 = s + yu * W;
    const float* r1 = s + qy * W;
    const float* r2 = s + yd * W;
    float a00 = r0[xl], a01 = r0[qx], a02 = r0[xr];
    float a10 = r1[xl], a11 = r1[qx], a12 = r1[xr];
    float a20 = r2[xl], a21 = r2[qx], a22 = r2[xr];
    float he0 = 0.125f * (a00 + a02) + 0.75f * a01;
    float he1 = 0.125f * (a10 + a12) + 0.75f * a11;
    float he2 = 0.125f * (a20 + a22) + 0.75f * a21;
    float ho0 = 0.5f * (a01 + a02);
    float ho1 = 0.5f * (a11 + a12);
    float ho2 = 0.5f * (a21 + a22);
    ee = 0.125f * (he0 + he2) + 0.75f * he1;
    eo = 0.125f * (ho0 + ho2) + 0.75f * ho1;
    oe = 0.5f * (he1 + he2);
    oo = 0.5f * (ho1 + ho2);
}

// ---------------------------------------------------------------------------
// Fused mid levels (1024-thread block per plane): dn2 -> dn3,dn4,dn5,F4,F3,F2.
// ---------------------------------------------------------------------------
#define FNT 1024
#define SM_DN2 0
#define SM_HB3 14400
#define SM_DN3 21600
#define SM_DN4 25200
#define SM_DN5 26120
#define SM_F4  26360
#define SM_TOT 27280   // 109120 bytes

__global__ void __launch_bounds__(FNT) fused_mid_kernel(
        const float* __restrict__ dn2,
        const float* __restrict__ colv, const float* __restrict__ rowv,
        const float* __restrict__ fixations,
        float* __restrict__ F2g) {
    extern __shared__ float sm[];
    float* s_dn2 = sm + SM_DN2;
    float* s_hb3 = sm + SM_HB3;
    float* s_F3  = sm + SM_HB3;   // overlay (hb3 dead after dn3)
    float* s_dn3 = sm + SM_DN3;
    float* s_dn4 = sm + SM_DN4;
    float* s_dn5 = sm + SM_DN5;
    float* s_F4  = sm + SM_F4;

    const int p = blockIdx.x;
    const int b = p / 3;
    const int t = threadIdx.x;
    const float k0 = 0.0625f, k1 = 0.25f, k2 = 0.375f;

    const float4* src4 = (const float4*)(dn2 + (size_t)p * (H2 * W2));
    for (int i = t; i < (H2 * W2) / 4; i += FNT) ((float4*)s_dn2)[i] = src4[i];
    __syncthreads();

    for (int idx = t; idx < H2 * W3; idx += FNT) {
        int y = idx / W3;
        int ox = idx - y * W3;
        const float* row = s_dn2 + y * W2;
        int xc = 2 * ox;
        float v;
        if (ox >= 1 && ox <= W3 - 2) {
            v = k0 * (row[xc - 2] + row[xc + 2]) + k1 * (row[xc - 1] + row[xc + 1])
              + k2 * row[xc];
        } else {
            v = k2 * row[xc]
              + k1 * (row[refl(xc - 1, W2)] + row[refl(xc + 1, W2)])
              + k0 * (row[refl(xc - 2, W2)] + row[refl(xc + 2, W2)]);
        }
        s_hb3[idx] = v;
    }
    __syncthreads();

    for (int idx = t; idx < H3 * W3; idx += FNT) {
        int oy = idx / W3;
        int ox = idx - oy * W3;
        int yc = 2 * oy;
        float v;
        if (oy >= 1 && oy <= H3 - 2) {
            v = k0 * (s_hb3[(yc - 2) * W3 + ox] + s_hb3[(yc + 2) * W3 + ox])
              + k1 * (s_hb3[(yc - 1) * W3 + ox] + s_hb3[(yc + 1) * W3 + ox])
              + k2 * s_hb3[yc * W3 + ox];
        } else {
            v = k2 * s_hb3[yc * W3 + ox]
              + k1 * (s_hb3[refl(yc - 1, H2) * W3 + ox] + s_hb3[refl(yc + 1, H2) * W3 + ox])
              + k0 * (s_hb3[refl(yc - 2, H2) * W3 + ox] + s_hb3[refl(yc + 2, H2) * W3 + ox]);
        }
        s_dn3[idx] = v;
    }
    __syncthreads();

    for (int idx = t; idx < H4 * W4; idx += FNT)
        s_dn4[idx] = pd2_at(s_dn3, H3, W3, idx / W4, idx % W4);
    __syncthreads();
    for (int idx = t; idx < H5 * W5; idx += FNT)
        s_dn5[idx] = pd2_at(s_dn4, H4, W4, idx / W5, idx % W5);
    __syncthreads();

    const float fxx = fixations[2 * b];
    const float fyy = fixations[2 * b + 1];

    {   // level 4
        int x1 = min(max((int)(40.0f - fxx * 0.0625f), 0), W3 - W4);
        int y1 = min(max((int)(22.5f - fyy * 0.0625f), 0), H3 - H4);
        const float* cv = colv + CO4 + y1;
        const float* rv = rowv + RO4 + x1;
        const int qH = (H4 + 1) / 2, qW = W4 / 2;
        for (int idx = t; idx < qH * qW; idx += FNT) {
            int qy = idx / qW;
            int qx = idx - qy * qW;
            float ee, eo, oe, oo;
            pyrup_quad(s_dn5, H5, W5, qy, qx, ee, eo, oe, oo);
            int y0 = 2 * qy, x0 = 2 * qx;
            float rw0 = rv[x0], rw1 = rv[x0 + 1];
            float cw0 = cv[y0];
            s_F4[y0 * W4 + x0]     = ee + (s_dn4[y0 * W4 + x0]     - ee) * (cw0 * rw0);
            s_F4[y0 * W4 + x0 + 1] = eo + (s_dn4[y0 * W4 + x0 + 1] - eo) * (cw0 * rw1);
            if (y0 + 1 < H4) {
                float cw1 = cv[y0 + 1];
                s_F4[(y0 + 1) * W4 + x0]     = oe + (s_dn4[(y0 + 1) * W4 + x0]     - oe) * (cw1 * rw0);
                s_F4[(y0 + 1) * W4 + x0 + 1] = oo + (s_dn4[(y0 + 1) * W4 + x0 + 1] - oo) * (cw1 * rw1);
            }
        }
    }
    __syncthreads();

    {   // level 3
        int x1 = min(max((int)(80.0f - fxx * 0.125f), 0), W2 - W3);
        int y1 = min(max((int)(45.0f - fyy * 0.125f), 0), H2 - H3);
        const float* cv = colv + CO3 + y1;
        const float* rv = rowv + RO3 + x1;
        const int qH = (H3 + 1) / 2, qW = W3 / 2;
        for (int idx = t; idx < qH * qW; idx += FNT) {
            int qy = idx / qW;
            int qx = idx - qy * qW;
            float Fee, Feo, Foe, Foo, Dee, Deo, Doe, Doo;
            pyrup_quad(s_F4, H4, W4, qy, qx, Fee, Feo, Foe, Foo);
            pyrup_quad(s_dn4, H4, W4, qy, qx, Dee, Deo, Doe, Doo);
            int y0 = 2 * qy, x0 = 2 * qx;
            float rw0 = rv[x0], rw1 = rv[x0 + 1];
            float cw0 = cv[y0];
            s_F3[y0 * W3 + x0]     = Fee + (s_dn3[y0 * W3 + x0]     - Dee) * (cw0 * rw0);
            s_F3[y0 * W3 + x0 + 1] = Feo + (s_dn3[y0 * W3 + x0 + 1] - Deo) * (cw0 * rw1);
            if (y0 + 1 < H3) {
                float cw1 = cv[y0 + 1];
                s_F3[(y0 + 1) * W3 + x0]     = Foe + (s_dn3[(y0 + 1) * W3 + x0]     - Doe) * (cw1 * rw0);
                s_F3[(y0 + 1) * W3 + x0 + 1] = Foo + (s_dn3[(y0 + 1) * W3 + x0 + 1] - Doo) * (cw1 * rw1);
            }
        }
    }
    __syncthreads();

    {   // level 2 -> global F2
        int x1 = min(max((int)(160.0f - fxx * 0.25f), 0), W1 - W2);
        int y1 = min(max((int)(90.0f - fyy * 0.25f), 0), H1 - H2);
        const float* cv = colv + CO2 + y1;
        const float* rv = rowv + RO2 + x1;
        float* g = F2g + (size_t)p * (H2 * W2);
        const int qH = H2 / 2, qW = W2 / 2;
        for (int idx = t; idx < qH * qW; idx += FNT) {
            int qy = idx / qW;
            int qx = idx - qy * qW;
            float Fee, Feo, Foe, Foo, Dee, Deo, Doe, Doo;
            pyrup_quad(s_F3, H3, W3, qy, qx, Fee, Feo, Foe, Foo);
            pyrup_quad(s_dn3, H3, W3, qy, qx, Dee, Deo, Doe, Doo);
            int y0 = 2 * qy, x0 = 2 * qx;
            float rw0 = rv[x0], rw1 = rv[x0 + 1];
            float cw0 = cv[y0], cw1 = cv[y0 + 1];
            float2 o0, o1;
            o0.x = Fee + (s_dn2[y0 * W2 + x0]     - Dee) * (cw0 * rw0);
            o0.y = Feo + (s_dn2[y0 * W2 + x0 + 1] - Deo) * (cw0 * rw1);
            o1.x = Foe + (s_dn2[(y0 + 1) * W2 + x0]     - Doe) * (cw1 * rw0);
            o1.y = Foo + (s_dn2[(y0 + 1) * W2 + x0 + 1] - Doo) * (cw1 * rw1);
            *(float2*)(g + y0 * W2 + x0) = o0;
            *(float2*)(g + (y0 + 1) * W2 + x0) = o1;
        }
    }
}

// ---------------------------------------------------------------------------
// recon01: merged level-1 + level-0 reconstruction.
// Block (16,16) -> 64x32 output pixels (32x16 level-0 quads).
// Stages dn1 (20x36) + F2/dn2 (12x20), computes the F1 tile as 10x18 quads
// in smem, then level-0 quad-pair epilogue vs images.
// ---------------------------------------------------------------------------
#define RQX 32
#define RQY 16

__global__ void __launch_bounds__(256) recon01(
        const float* __restrict__ F2,
        const float* __restrict__ dn2,
        const float* __restrict__ dn1,
        const float* __restrict__ images,
        const float* __restrict__ colv,
        const float* __restrict__ rowv,
        const float* __restrict__ fixations,
        float* __restrict__ out) {
    __shared__ float sD1[20][36];
    __shared__ float sF1[20][36];
    __shared__ float sF2[12][20];
    __shared__ float sD2[12][20];

    const int p = blockIdx.z;
    const int b = p / 3;
    const int qx0 = blockIdx.x * RQX;   // level-1 pixel x of first quad
    const int qy0 = blockIdx.y * RQY;
    const int tid = threadIdx.y * 16 + threadIdx.x;

    const float fxx = fixations[2 * b];
    const float fyy = fixations[2 * b + 1];
    const int x1_0 = min(max((int)(639.5f - fxx), 0), 1279 - W0);
    const int y1_0 = min(max((int)(359.5f - fyy), 0), 719 - H0);
    const int x1_1 = min(max((int)(320.0f - fxx * 0.5f), 0), W0 - W1);
    const int y1_1 = min(max((int)(180.0f - fyy * 0.5f), 0), H0 - H1);

    const int base1y = qy0 - 2, base1x = qx0 - 2;
    const int base2y = (qy0 >> 1) - 2, base2x = (qx0 >> 1) - 2;

    // ---- stage dn1 (20x36) and F2/dn2 (12x20), clamped -----------------------
    {
        const float* s1 = dn1 + (size_t)p * (H1 * W1);
        for (int i = tid; i < 20 * 36; i += 256) {
            int r = i / 36;
            int c = i - r * 36;
            int gr = min(max(base1y + r, 0), H1 - 1);
            int gc = min(max(base1x + c, 0), W1 - 1);
            sD1[r][c] = s1[(size_t)gr * W1 + gc];
        }
        const float* sf = F2 + (size_t)p * (H2 * W2);
        const float* sd = dn2 + (size_t)p * (H2 * W2);
        for (int i = tid; i < 12 * 20; i += 256) {
            int r = i / 20;
            int c = i - r * 20;
            int gr = min(max(base2y + r, 0), H2 - 1);
            int gc = min(max(base2x + c, 0), W2 - 1);
            size_t off = (size_t)gr * W2 + gc;
            sF2[r][c] = sf[off];
            sD2[r][c] = sd[off];
        }
    }
    __syncthreads();

    // ---- compute F1 tile: 10x18 quads, one per thread -----------------------
    {
        const float* cv1 = colv + CO1 + y1_1;
        const float* rv1 = rowv + RO1 + x1_1;
        const int Qy0 = (qy0 >> 1) - 1;
        const int Qx0 = (qx0 >> 1) - 1;
        for (int i = tid; i < 10 * 18; i += 256) {
            int qr = i / 18;
            int qc = i - qr * 18;
            int Qy = Qy0 + qr;
            int Qx = Qx0 + qc;
            if (Qy < 0 || Qy >= H2 || Qx < 0 || Qx >= W2) continue;

            int yu = ((Qy == 0) ? 1 : Qy - 1) - base2y;
            int yc = Qy - base2y;
            int yd = ((Qy < H2 - 1) ? Qy + 1 : H2 - 1) - base2y;
            int xl = ((Qx == 0) ? 1 : Qx - 1) - base2x;
            int xc = Qx - base2x;
            int xr = ((Qx < W2 - 1) ? Qx + 1 : W2 - 1) - base2x;

            float Fee, Feo, Foe, Foo, Dee, Deo, Doe, Doo;
            {
                float a00 = sF2[yu][xl], a01 = sF2[yu][xc], a02 = sF2[yu][xr];
                float a10 = sF2[yc][xl], a11 = sF2[yc][xc], a12 = sF2[yc][xr];
                float a20 = sF2[yd][xl], a21 = sF2[yd][xc], a22 = sF2[yd][xr];
                float he0 = 0.125f * (a00 + a02) + 0.75f * a01;
                float he1 = 0.125f * (a10 + a12) + 0.75f * a11;
                float he2 = 0.125f * (a20 + a22) + 0.75f * a21;
                float ho0 = 0.5f * (a01 + a02);
                float ho1 = 0.5f * (a11 + a12);
                float ho2 = 0.5f * (a21 + a22);
                Fee = 0.125f * (he0 + he2) + 0.75f * he1;
                Feo = 0.125f * (ho0 + ho2) + 0.75f * ho1;
                Foe = 0.5f * (he1 + he2);
                Foo = 0.5f * (ho1 + ho2);
            }
            {
                float a00 = sD2[yu][xl], a01 = sD2[yu][xc], a02 = sD2[yu][xr];
                float a10 = sD2[yc][xl], a11 = sD2[yc][xc], a12 = sD2[yc][xr];
                float a20 = sD2[yd][xl], a21 = sD2[yd][xc], a22 = sD2[yd][xr];
                float he0 = 0.125f * (a00 + a02) + 0.75f * a01;
                float he1 = 0.125f * (a10 + a12) + 0.75f * a11;
                float he2 = 0.125f * (a20 + a22) + 0.75f * a21;
                float ho0 = 0.5f * (a01 + a02);
                float ho1 = 0.5f * (a11 + a12);
                float ho2 = 0.5f * (a21 + a22);
                Dee = 0.125f * (he0 + he2) + 0.75f * he1;
                Deo = 0.125f * (ho0 + ho2) + 0.75f * ho1;
                Doe = 0.5f * (he1 + he2);
                Doo = 0.5f * (ho1 + ho2);
            }

            int gy = 2 * Qy, gx = 2 * Qx;
            int r0 = gy - base1y;
            int c0 = gx - base1x;
            float cw0 = cv1[gy], cw1 = cv1[gy + 1];
            float rw0 = rv1[gx], rw1 = rv1[gx + 1];
            sF1[r0][c0]         = Fee + (sD1[r0][c0]         - Dee) * (cw0 * rw0);
            sF1[r0][c0 + 1]     = Feo + (sD1[r0][c0 + 1]     - Deo) * (cw0 * rw1);
            sF1[r0 + 1][c0]     = Foe + (sD1[r0 + 1][c0]     - Doe) * (cw1 * rw0);
            sF1[r0 + 1][c0 + 1] = Foo + (sD1[r0 + 1][c0 + 1] - Doo) * (cw1 * rw1);
        }
    }
    __syncthreads();

    // ---- level-0 recon: two quads per thread, float4 rows -------------------
    const int ty = threadIdx.y;
    const int qy = qy0 + ty;
    if (qy >= H1) return;
    const int qxA = qx0 + 2 * threadIdx.x;

    // tile-local (slot = global - base, base = qy0-2 / qx0-2)
    const int cb = 2 * threadIdx.x + 2;
    const int la = (qxA == 0) ? 3 : cb - 1;
    const int rb = (qxA + 1 < W1 - 1) ? cb + 2 : (W1 + 1 - qx0);
    const int rc = ty + 2;
    const int ru = (qy == 0) ? 3 : ty + 1;
    const int rd = (qy < H1 - 1) ? ty + 3 : ty + 2;

    float FheA[3], FhoA[3], FheB[3], FhoB[3];
    float DheA[3], DhoA[3], DheB[3], DhoB[3];
    int rows[3] = {ru, rc, rd};
#pragma unroll
    for (int i = 0; i < 3; i++) {
        int r = rows[i];
        {
            float vl = sF1[r][la], v0 = sF1[r][cb], v1 = sF1[r][cb + 1], vr = sF1[r][rb];
            FheA[i] = 0.125f * (vl + v1) + 0.75f * v0;
            FhoA[i] = 0.5f * (v0 + v1);
            FheB[i] = 0.125f * (v0 + vr) + 0.75f * v1;
            FhoB[i] = 0.5f * (v1 + vr);
        }
        {
            float vl = sD1[r][la], v0 = sD1[r][cb], v1 = sD1[r][cb + 1], vr = sD1[r][rb];
            DheA[i] = 0.125f * (vl + v1) + 0.75f * v0;
            DhoA[i] = 0.5f * (v0 + v1);
            DheB[i] = 0.125f * (v0 + vr) + 0.75f * v1;
            DhoB[i] = 0.5f * (v1 + vr);
        }
    }

    const int x0 = 2 * qxA;
    const int y0 = 2 * qy;
    const size_t obase = (size_t)p * (H0 * W0);
    const float* rv = rowv + RO0 + x1_0 + x0;
    float rw0 = rv[0], rw1 = rv[1], rw2 = rv[2], rw3 = rv[3];
    float cw0 = colv[CO0 + y0 + y1_0], cw1 = colv[CO0 + y0 + 1 + y1_0];

    {
        float uF0 = 0.125f * (FheA[0] + FheA[2]) + 0.75f * FheA[1];
        float uF1 = 0.125f * (FhoA[0] + FhoA[2]) + 0.75f * FhoA[1];
        float uF2 = 0.125f * (FheB[0] + FheB[2]) + 0.75f * FheB[1];
        float uF3 = 0.125f * (FhoB[0] + FhoB[2]) + 0.75f * FhoB[1];
        float uD0 = 0.125f * (DheA[0] + DheA[2]) + 0.75f * DheA[1];
        float uD1 = 0.125f * (DhoA[0] + DhoA[2]) + 0.75f * DhoA[1];
        float uD2 = 0.125f * (DheB[0] + DheB[2]) + 0.75f * DheB[1];
        float uD3 = 0.125f * (DhoB[0] + DhoB[2]) + 0.75f * DhoB[1];
        const float4 dc = *(const float4*)(images + obase + (size_t)y0 * W0 + x0);
        float4 o;
        o.x = uF0 + (dc.x - uD0) * (cw0 * rw0);
        o.y = uF1 + (dc.y - uD1) * (cw0 * rw1);
        o.z = uF2 + (dc.z - uD2) * (cw0 * rw2);
        o.w = uF3 + (dc.w - uD3) * (cw0 * rw3);
        *(float4*)(out + obase + (size_t)y0 * W0 + x0) = o;
    }
    {
        float uF0 = 0.5f * (FheA[1] + FheA[2]);
        float uF1 = 0.5f * (FhoA[1] + FhoA[2]);
        float uF2 = 0.5f * (FheB[1] + FheB[2]);
        float uF3 = 0.5f * (FhoB[1] + FhoB[2]);
        float uD0 = 0.5f * (DheA[1] + DheA[2]);
        float uD1 = 0.5f * (DhoA[1] + DhoA[2]);
        float uD2 = 0.5f * (DheB[1] + DheB[2]);
        float uD3 = 0.5f * (DhoB[1] + DhoB[2]);
        const float4 dc = *(const float4*)(images + obase + (size_t)(y0 + 1) * W0 + x0);
        float4 o;
        o.x = uF0 + (dc.x - uD0) * (cw1 * rw0);
        o.y = uF1 + (dc.y - uD1) * (cw1 * rw1);
        o.z = uF2 + (dc.z - uD2) * (cw1 * rw2);
        o.w = uF3 + (dc.w - uD3) * (cw1 * rw3);
        *(float4*)(out + obase + (size_t)(y0 + 1) * W0 + x0) = o;
    }
}

// ---------------------------------------------------------------------------

static inline int idiv(int a, int b) { return (a + b - 1) / b; }

extern "C" void kernel_launch(void* const* d_in, const int* in_sizes, int n_in,
                              void* d_out, int out_size) {
    (void)in_sizes; (void)n_in; (void)out_size;
    const float* images = (const float*)d_in[0];
    const float* fix    = (const float*)d_in[1];
    float* out = (float*)d_out;

    float *rowv, *colv, *dn1, *dn2, *F2;
    cudaGetSymbolAddress((void**)&rowv, g_rowv);
    cudaGetSymbolAddress((void**)&colv, g_colv);
    cudaGetSymbolAddress((void**)&dn1, g_dn1);
    cudaGetSymbolAddress((void**)&dn2, g_dn2);
    cudaGetSymbolAddress((void**)&F2, g_F2);

    cudaFuncSetAttribute(fused_mid_kernel,
                         cudaFuncAttributeMaxDynamicSharedMemorySize,
                         SM_TOT * (int)sizeof(float));

    gen_filters_kernel<<<1, 1024>>>(rowv, colv);

    {
        dim3 blk(16, 16);
        dim3 g1(idiv(W1, PTX), idiv(H1, PTY), NPL);
        pyrdown_st<<<g1, blk>>>(images, dn1, H0, W0, H1, W1);
        dim3 g2(idiv(W2, PTX), idiv(H2, PTY), NPL);
        pyrdown_st<<<g2, blk>>>(dn1, dn2, H1, W1, H2, W2);
    }

    fused_mid_kernel<<<NPL, FNT, SM_TOT * (int)sizeof(float)>>>(
        dn2, colv, rowv, fix, F2);

    {
        dim3 blk(16, 16);
        dim3 g0((W0 / 2) / RQX, idiv(H0 / 2, RQY), NPL);   // (10, 12, 96)
        recon01<<<g0, blk>>>(F2, dn2, dn1, images, colv, rowv, fix, out);
    }
}